// round 14
// baseline (speedup 1.0000x reference)
#include <cuda_runtime.h>
#include <cstdint>

// ---------------------------------------------------------------------------
// Problem constants
// ---------------------------------------------------------------------------
#define N_ROWS 16384      // 64 * 256
#define N_FEAT 2048
#define N_BINS 32
#define NSTRIPE 1024               // one stripe per 16-row tile
#define TBL 65536
#define NTILE 128                  // 128-row tiles
#define NG 64                      // 32-col groups over full K
#define NT16 (N_ROWS / 16)         // 1024 16-row fragments
// k_project dynamic smem: RP full 64KB + 2 x 64KB A chunk buffers + soff
#define PROJ_SMEM (65536 * 3 + 128)   // 196736

// ---------------------------------------------------------------------------
// Scratch (static device globals; no runtime allocation)
// ---------------------------------------------------------------------------
__device__ __align__(16) unsigned int g_xpack8[(size_t)NT16 * NG * 32 * 4]; // e4m3 x (32MB)
__device__ float              g_psum[(size_t)NSTRIPE * N_FEAT];   // 8MB
__device__ float              g_psq [(size_t)NSTRIPE * N_FEAT];   // 8MB
__device__ float              g_isig[N_FEAT];
__device__ float              g_m2  [N_FEAT];              // mean * isig
__device__ float              g_off [N_BINS];              // 256 * (m2 . RP)
__device__ __align__(16) unsigned int g_rppack8[512 * 32]; // e4m3x4 256*isig*RP, swizzled
__device__ unsigned int       g_hash[N_ROWS];
__device__ unsigned int       g_slot[N_ROWS];
__device__ unsigned long long g_tkey[TBL];
__device__ unsigned int       g_tcnt[TBL];
__device__ unsigned int       g_statsdone;     // stats blocks completed
__device__ unsigned int       g_projdone;      // project blocks completed

// ---------------------------------------------------------------------------
// Helpers
// ---------------------------------------------------------------------------
__device__ __forceinline__ unsigned pack8x4(float f0, float f1, float f2, float f3) {
    unsigned d;
    asm("{\n\t"
        ".reg .b16 lo, hi;\n\t"
        "cvt.rn.satfinite.e4m3x2.f32 lo, %2, %1;\n\t"
        "cvt.rn.satfinite.e4m3x2.f32 hi, %4, %3;\n\t"
        "mov.b32 %0, {lo, hi};\n\t"
        "}" : "=r"(d) : "f"(f0), "f"(f1), "f"(f2), "f"(f3));
    return d;
}

__device__ __forceinline__ void mma16832(float* c,
                                         unsigned a0, unsigned a1, unsigned a2, unsigned a3,
                                         unsigned b0, unsigned b1) {
    asm volatile(
        "mma.sync.aligned.m16n8k32.row.col.f32.e4m3.e4m3.f32 "
        "{%0,%1,%2,%3}, {%4,%5,%6,%7}, {%8,%9}, {%0,%1,%2,%3};"
        : "+f"(c[0]), "+f"(c[1]), "+f"(c[2]), "+f"(c[3])
        : "r"(a0), "r"(a1), "r"(a2), "r"(a3), "r"(b0), "r"(b1));
}

__device__ __forceinline__ uint32_t smaddr(const void* p) {
    return (uint32_t)__cvta_generic_to_shared(p);
}

__device__ __forceinline__ void cpa16(uint32_t dst, const void* src) {
    asm volatile("cp.async.cg.shared.global [%0], [%1], 16;" :: "r"(dst), "l"(src));
}

template<int N> __device__ __forceinline__ void cpa_wait() {
    asm volatile("cp.async.wait_group %0;" :: "n"(N) : "memory");
}

__device__ __forceinline__ void table_insert(int i, unsigned h) {
    unsigned long long key = ((unsigned long long)h << 6) | (unsigned long long)(i & 63);
    unsigned long long m = key * 0x9E3779B97F4A7C15ULL;
    unsigned s = (unsigned)(m >> 48);   // 16-bit slot
    for (;;) {
        unsigned long long prev = atomicCAS(&g_tkey[s], ~0ULL, key);
        if (prev == ~0ULL || prev == key) {
            atomicAdd(&g_tcnt[s], 1u);
            g_slot[i] = s;
            return;
        }
        s = (s + 1) & (TBL - 1);
    }
}

// ---------------------------------------------------------------------------
// Kernel 1 (fused): column partial sums + e4m3 fragment pack + table inits.
//   blocks [0,1024): one per tile16 (FROZEN since R11, measured 28.4us).
//   blocks [1024,1280): hash-table init + counters.
// ---------------------------------------------------------------------------
__global__ void __launch_bounds__(256, 4) k_pre(const float* __restrict__ x) {
    int b = blockIdx.x;
    if (b < 1024) {
        int tid = threadIdx.x;
        int g = tid >> 2, qp = tid & 3;
        int f0 = g * 8 + qp;                // float4 slot, khalf=0
        int f1 = f0 + 4;                    // float4 slot, khalf=1
        const float4* x4 = (const float4*)x;
        uint4* xp4 = (uint4*)g_xpack8;

        size_t rbase = (size_t)b * 16 * 512;               // float4 units
        size_t wbase = ((size_t)b * NG + g) * 32 + qp;     // uint4 units

        float s[8], qq[8];
#pragma unroll
        for (int j = 0; j < 8; j++) { s[j] = 0.f; qq[j] = 0.f; }

#pragma unroll 2
        for (int rr = 0; rr < 8; rr++) {
            size_t rA = rbase + (size_t)rr * 512;
            size_t rB = rA + 8 * 512;
            float4 vA0 = x4[rA + f0];
            float4 vA1 = x4[rA + f1];
            float4 vB0 = x4[rB + f0];
            float4 vB1 = x4[rB + f1];

            s[0] += vA0.x + vB0.x; qq[0] += vA0.x*vA0.x + vB0.x*vB0.x;
            s[1] += vA0.y + vB0.y; qq[1] += vA0.y*vA0.y + vB0.y*vB0.y;
            s[2] += vA0.z + vB0.z; qq[2] += vA0.z*vA0.z + vB0.z*vB0.z;
            s[3] += vA0.w + vB0.w; qq[3] += vA0.w*vA0.w + vB0.w*vB0.w;
            s[4] += vA1.x + vB1.x; qq[4] += vA1.x*vA1.x + vB1.x*vB1.x;
            s[5] += vA1.y + vB1.y; qq[5] += vA1.y*vA1.y + vB1.y*vB1.y;
            s[6] += vA1.z + vB1.z; qq[6] += vA1.z*vA1.z + vB1.z*vB1.z;
            s[7] += vA1.w + vB1.w; qq[7] += vA1.w*vA1.w + vB1.w*vB1.w;

            uint4 w;
            w.x = pack8x4(vA0.x, vA0.y, vA0.z, vA0.w);
            w.y = pack8x4(vB0.x, vB0.y, vB0.z, vB0.w);
            w.z = pack8x4(vA1.x, vA1.y, vA1.z, vA1.w);
            w.w = pack8x4(vB1.x, vB1.y, vB1.z, vB1.w);
            xp4[wbase + (size_t)rr * 4] = w;
        }

        int c0 = g * 32 + qp * 4;
        *(float4*)(g_psum + (size_t)b * N_FEAT + c0)      = make_float4(s[0], s[1], s[2], s[3]);
        *(float4*)(g_psum + (size_t)b * N_FEAT + c0 + 16) = make_float4(s[4], s[5], s[6], s[7]);
        *(float4*)(g_psq  + (size_t)b * N_FEAT + c0)      = make_float4(qq[0], qq[1], qq[2], qq[3]);
        *(float4*)(g_psq  + (size_t)b * N_FEAT + c0 + 16) = make_float4(qq[4], qq[5], qq[6], qq[7]);
    } else {
        int i = (b - 1024) * 256 + threadIdx.x;
        g_tkey[i] = ~0ULL;
        g_tcnt[i] = 0u;
        if (b == 1024 && threadIdx.x == 0) { g_statsdone = 0u; g_projdone = 0u; }
    }
}

// ---------------------------------------------------------------------------
// Kernel 2 (fused stats + scale, device-side gate):
//   blocks [0,256): RunningMeanStd finalize -> isig, m2; release g_statsdone.
//   blocks [256,321): spin until g_statsdone==256, then RP pack / offset.
//   All 321 blocks are co-resident (tiny), so the spin cannot deadlock.
// ---------------------------------------------------------------------------
__global__ void k_statscale(const float* __restrict__ rp) {
    int b = blockIdx.x;
    if (b < 256) {
        __shared__ float ss[32][8], sq[32][8];
        int c = threadIdx.x & 7, g = threadIdx.x >> 3;
        int col = b * 8 + c;
        float s = 0.f, q = 0.f;
#pragma unroll 4
        for (int st = g; st < NSTRIPE; st += 32) {
            s += g_psum[(size_t)st * N_FEAT + col];
            q += g_psq [(size_t)st * N_FEAT + col];
        }
        ss[g][c] = s; sq[g][c] = q;
        __syncthreads();
        if (g == 0) {
#pragma unroll
            for (int j = 1; j < 32; j++) { s += ss[j][c]; q += sq[j][c]; }
            const float n = 16384.0f;
            float bm = s / n;
            float bv = (q - bm * bm * n) / (n - 1.0f);       // unbiased variance
            const double nd = 16384.0, totd = 1e-4 + nd;
            float mean = bm * (float)(nd / totd);
            float m2v  = (1e-4f + bv * 16384.0f) + (bm * bm) * (float)(1e-4 * nd / totd);
            float var  = m2v / (float)totd;
            float isg  = 1.0f / sqrtf(var + 1e-8f);
            g_isig[col] = isg;
            g_m2[col]   = mean * isg;
            __threadfence();                 // release this block's writes
        }
        __syncthreads();
        if (threadIdx.x == 0) atomicAdd(&g_statsdone, 1u);
    } else {
        // gate: wait for all 256 stats blocks
        if (threadIdx.x == 0) {
            while (atomicAdd(&g_statsdone, 0u) < 256u) { }
        }
        __syncthreads();
        __threadfence();                     // acquire isig/m2

        int bb = b - 256;
        if (bb < 64) {
            int idx = bb * 256 + threadIdx.x;          // 0..16383
            int k4 = idx >> 5;                         // 4-col k word 0..511
            int n  = idx & 31;
            float f0 = rp[(4 * k4 + 0) * N_BINS + n] * g_isig[4 * k4 + 0] * 256.0f;
            float f1 = rp[(4 * k4 + 1) * N_BINS + n] * g_isig[4 * k4 + 1] * 256.0f;
            float f2 = rp[(4 * k4 + 2) * N_BINS + n] * g_isig[4 * k4 + 2] * 256.0f;
            float f3 = rp[(4 * k4 + 3) * N_BINS + n] * g_isig[4 * k4 + 3] * 256.0f;
            int scol = n ^ ((k4 & 3) << 3);
            g_rppack8[k4 * 32 + scol] = pack8x4(f0, f1, f2, f3);
        } else {
            __shared__ float red[8][32];
            int n = threadIdx.x & 31, part = threadIdx.x >> 5;   // 8 parts x 256 k
            float s = 0.f;
            for (int k = part * 256; k < part * 256 + 256; k++)
                s = fmaf(g_m2[k], rp[k * N_BINS + n], s);
            red[part][n] = s;
            __syncthreads();
            if (part == 0) {
#pragma unroll
                for (int j = 1; j < 8; j++) s += red[j][n];
                g_off[n] = s * 256.0f;
            }
        }
    }
}

// ---------------------------------------------------------------------------
// Kernel 3: FULL-K e4m3 mma projection (core FROZEN from R13, 22.1us) +
//   fused rewards tail: last-arriving block computes out[] for all rows.
// ---------------------------------------------------------------------------
__global__ void __launch_bounds__(256, 1) k_project(float* __restrict__ out) {
    extern __shared__ unsigned smem[];
    unsigned* srp = smem;                        // [0,16384) words: RP full
    unsigned* sa0 = smem + 16384;                // A buffer 0 (16384 words)
    unsigned* sa1 = smem + 32768;                // A buffer 1
    float* soff   = (float*)(smem + 49152);      // [32]
    __shared__ int s_lastblk;

    int tile = blockIdx.x;
    int tid  = threadIdx.x;

    // stage RP full (4096 x 16B) + A chunk 0 -> group 0
    {
        const char* src = (const char*)g_rppack8;
        uint32_t dst = smaddr(srp);
#pragma unroll
        for (int i = 0; i < 16; i++) {
            int idx = tid + i * 256;
            cpa16(dst + idx * 16, src + idx * 16);
        }
    }
    {
        uint32_t dst = smaddr(sa0);
#pragma unroll
        for (int i = 0; i < 16; i++) {
            int idx = tid + i * 256;
            int w = idx >> 9, inner = idx & 511;
            const char* src = (const char*)g_xpack8 +
                (((size_t)(tile * 8 + w) * NG + 0 * 16) * 512 + (size_t)inner * 16);
            cpa16(dst + idx * 16, src);
        }
    }
    if (tid < 32) soff[tid] = g_off[tid];
    asm volatile("cp.async.commit_group;");
    {
        uint32_t dst = smaddr(sa1);
#pragma unroll
        for (int i = 0; i < 16; i++) {
            int idx = tid + i * 256;
            int w = idx >> 9, inner = idx & 511;
            const char* src = (const char*)g_xpack8 +
                (((size_t)(tile * 8 + w) * NG + 1 * 16) * 512 + (size_t)inner * 16);
            cpa16(dst + idx * 16, src);
        }
    }
    asm volatile("cp.async.commit_group;");

    int warp = tid >> 5, lane = tid & 31;
    int q = lane & 3, r = lane >> 2;
    int tile16 = tile * 8 + warp;
    int rowA = tile16 * 16 + r, rowB = rowA + 8;

    float acc[4][4];
#pragma unroll
    for (int t = 0; t < 4; t++)
#pragma unroll
        for (int c = 0; c < 4; c++) acc[t][c] = 0.f;

    unsigned scol[4];
#pragma unroll
    for (int t = 0; t < 4; t++) scol[t] = (unsigned)((t * 8 + r) ^ (q << 3));

#pragma unroll
    for (int kq = 0; kq < 4; kq++) {
        if (kq < 3) cpa_wait<1>(); else cpa_wait<0>();
        __syncthreads();

        unsigned* sa = (kq & 1) ? sa1 : sa0;
        const uint4* ap = (const uint4*)sa + warp * 512 + lane;
#pragma unroll
        for (int gg = 0; gg < 16; gg++) {            // 16 groups of 32 k-cols
            uint4 a = ap[gg * 32];                   // fragment regs (LDS.128)
            int g = kq * 16 + gg;
            int w0 = (g * 8 + q) * 32;
            int w1 = (g * 8 + q + 4) * 32;
#pragma unroll
            for (int t = 0; t < 4; t++) {
                unsigned b0 = srp[w0 + scol[t]];
                unsigned b1 = srp[w1 + scol[t]];
                mma16832(acc[t], a.x, a.y, a.z, a.w, b0, b1);
            }
        }
        __syncthreads();

        if (kq < 2) {    // stage chunk kq+2 into the buffer just freed
            unsigned* dstbuf = (kq & 1) ? sa1 : sa0;
            uint32_t dst = smaddr(dstbuf);
            int kn = kq + 2;
#pragma unroll
            for (int i = 0; i < 16; i++) {
                int idx = tid + i * 256;
                int w = idx >> 9, inner = idx & 511;
                const char* src = (const char*)g_xpack8 +
                    (((size_t)(tile * 8 + w) * NG + kn * 16) * 512 + (size_t)inner * 16);
                cpa16(dst + idx * 16, src);
            }
            asm volatile("cp.async.commit_group;");
        }
    }

    // full-K accumulators -> offset-subtract -> sign bits -> hash -> insert
    unsigned mlo = 0u, mhi = 0u;
#pragma unroll
    for (int t = 0; t < 4; t++) {
        int cb = t * 8 + 2 * q;
        float o0 = soff[cb], o1 = soff[cb + 1];
        mlo |= ((acc[t][0] - o0) > 0.f ? 1u : 0u) << cb;
        mlo |= ((acc[t][1] - o1) > 0.f ? 1u : 0u) << (cb + 1);
        mhi |= ((acc[t][2] - o0) > 0.f ? 1u : 0u) << cb;
        mhi |= ((acc[t][3] - o1) > 0.f ? 1u : 0u) << (cb + 1);
    }
    mlo |= __shfl_xor_sync(0xffffffffu, mlo, 1);
    mlo |= __shfl_xor_sync(0xffffffffu, mlo, 2);
    mhi |= __shfl_xor_sync(0xffffffffu, mhi, 1);
    mhi |= __shfl_xor_sync(0xffffffffu, mhi, 2);

    if (q == 0) {
        g_hash[rowA] = mlo;
        g_hash[rowB] = mhi;
        table_insert(rowA, mlo);
        table_insert(rowB, mhi);
    }

    // --- fused rewards tail: last-arriving block finalizes out[] ---
    __threadfence();                  // release this block's hash/slot/counts
    __syncthreads();
    if (tid == 0) s_lastblk = (int)atomicAdd(&g_projdone, 1u);
    __syncthreads();
    if (s_lastblk != NTILE - 1) return;
    __threadfence();                  // acquire all blocks' inserts

    for (int i = tid; i < N_ROWS; i += 256) {
        unsigned s = g_slot[i];
        float v = 1.0f;
        if (g_tcnt[s] != 1u) {
            unsigned long long my = ((unsigned long long)g_hash[i] << 6) | (unsigned long long)(i & 63);
            int c = 1;
            for (int j = 0; j < i; j++) {
                unsigned long long kj = ((unsigned long long)g_hash[j] << 6) | (unsigned long long)(j & 63);
                c += (kj == my) ? 1 : 0;
            }
            v = 1.0f / sqrtf((float)c);
        }
        out[i] = v;
    }
}

// ---------------------------------------------------------------------------
// Launch (3 launches)
// ---------------------------------------------------------------------------
extern "C" void kernel_launch(void* const* d_in, const int* in_sizes, int n_in,
                              void* d_out, int out_size) {
    const float* x  = (const float*)d_in[0];
    const float* rp = (const float*)d_in[1];
    if (in_sizes[0] == N_FEAT * N_BINS) {   // defensive: swap if order differs
        const float* t = x; x = rp; rp = t;
    }
    float* out = (float*)d_out;

    cudaFuncSetAttribute(k_project, cudaFuncAttributeMaxDynamicSharedMemorySize, PROJ_SMEM);

    k_pre      <<<1280, 256>>>(x);
    k_statscale<<<321, 256>>>(rp);
    k_project  <<<NTILE, 256, PROJ_SMEM>>>(out);
}

// round 15
// speedup vs baseline: 1.5174x; 1.5174x over previous
#include <cuda_runtime.h>
#include <cstdint>

// ---------------------------------------------------------------------------
// Problem constants
// ---------------------------------------------------------------------------
#define N_ROWS 16384      // 64 * 256
#define N_FEAT 2048
#define N_BINS 32
#define NSTRIPE 1024               // one stripe per 16-row tile
#define TBL 65536
#define NTILE 128                  // 128-row tiles
#define NG 64                      // 32-col groups over full K
#define NT16 (N_ROWS / 16)         // 1024 16-row fragments
// k_project dynamic smem: RP full 64KB + 2 x 64KB A chunk buffers + soff
#define PROJ_SMEM (65536 * 3 + 128)   // 196736

// ---------------------------------------------------------------------------
// Scratch (static device globals; no runtime allocation)
// ---------------------------------------------------------------------------
__device__ __align__(16) unsigned int g_xpack8[(size_t)NT16 * NG * 32 * 4]; // e4m3 x (32MB)
__device__ float              g_psum[(size_t)NSTRIPE * N_FEAT];   // 8MB
__device__ float              g_psq [(size_t)NSTRIPE * N_FEAT];   // 8MB
__device__ float              g_isig[N_FEAT];
__device__ float              g_m2  [N_FEAT];              // mean * isig
__device__ float              g_off [N_BINS];              // 256 * (m2 . RP)
__device__ __align__(16) unsigned int g_rppack8[512 * 32]; // e4m3x4 256*isig*RP, swizzled
__device__ unsigned int       g_hash[N_ROWS];
__device__ unsigned int       g_slot[N_ROWS];
__device__ unsigned long long g_tkey[TBL];
__device__ unsigned int       g_tcnt[TBL];

// ---------------------------------------------------------------------------
// Helpers
// ---------------------------------------------------------------------------
__device__ __forceinline__ unsigned pack8x4(float f0, float f1, float f2, float f3) {
    unsigned d;
    asm("{\n\t"
        ".reg .b16 lo, hi;\n\t"
        "cvt.rn.satfinite.e4m3x2.f32 lo, %2, %1;\n\t"
        "cvt.rn.satfinite.e4m3x2.f32 hi, %4, %3;\n\t"
        "mov.b32 %0, {lo, hi};\n\t"
        "}" : "=r"(d) : "f"(f0), "f"(f1), "f"(f2), "f"(f3));
    return d;
}

__device__ __forceinline__ void mma16832(float* c,
                                         unsigned a0, unsigned a1, unsigned a2, unsigned a3,
                                         unsigned b0, unsigned b1) {
    asm volatile(
        "mma.sync.aligned.m16n8k32.row.col.f32.e4m3.e4m3.f32 "
        "{%0,%1,%2,%3}, {%4,%5,%6,%7}, {%8,%9}, {%0,%1,%2,%3};"
        : "+f"(c[0]), "+f"(c[1]), "+f"(c[2]), "+f"(c[3])
        : "r"(a0), "r"(a1), "r"(a2), "r"(a3), "r"(b0), "r"(b1));
}

__device__ __forceinline__ uint32_t smaddr(const void* p) {
    return (uint32_t)__cvta_generic_to_shared(p);
}

__device__ __forceinline__ void cpa16(uint32_t dst, const void* src) {
    asm volatile("cp.async.cg.shared.global [%0], [%1], 16;" :: "r"(dst), "l"(src));
}

template<int N> __device__ __forceinline__ void cpa_wait() {
    asm volatile("cp.async.wait_group %0;" :: "n"(N) : "memory");
}

__device__ __forceinline__ void table_insert(int i, unsigned h) {
    unsigned long long key = ((unsigned long long)h << 6) | (unsigned long long)(i & 63);
    unsigned long long m = key * 0x9E3779B97F4A7C15ULL;
    unsigned s = (unsigned)(m >> 48);   // 16-bit slot
    for (;;) {
        unsigned long long prev = atomicCAS(&g_tkey[s], ~0ULL, key);
        if (prev == ~0ULL || prev == key) {
            atomicAdd(&g_tcnt[s], 1u);
            g_slot[i] = s;
            return;
        }
        s = (s + 1) & (TBL - 1);
    }
}

// ---------------------------------------------------------------------------
// Kernel 1 (fused): column partial sums + e4m3 fragment pack + table inits.
//   blocks [0,1024): one per tile16 (FROZEN since R11, measured 28.4us).
//   blocks [1024,1280): hash-table init.
// ---------------------------------------------------------------------------
__global__ void __launch_bounds__(256, 4) k_pre(const float* __restrict__ x) {
    int b = blockIdx.x;
    if (b < 1024) {
        int tid = threadIdx.x;
        int g = tid >> 2, qp = tid & 3;
        int f0 = g * 8 + qp;                // float4 slot, khalf=0
        int f1 = f0 + 4;                    // float4 slot, khalf=1
        const float4* x4 = (const float4*)x;
        uint4* xp4 = (uint4*)g_xpack8;

        size_t rbase = (size_t)b * 16 * 512;               // float4 units
        size_t wbase = ((size_t)b * NG + g) * 32 + qp;     // uint4 units

        float s[8], qq[8];
#pragma unroll
        for (int j = 0; j < 8; j++) { s[j] = 0.f; qq[j] = 0.f; }

#pragma unroll 2
        for (int rr = 0; rr < 8; rr++) {
            size_t rA = rbase + (size_t)rr * 512;
            size_t rB = rA + 8 * 512;
            float4 vA0 = x4[rA + f0];
            float4 vA1 = x4[rA + f1];
            float4 vB0 = x4[rB + f0];
            float4 vB1 = x4[rB + f1];

            s[0] += vA0.x + vB0.x; qq[0] += vA0.x*vA0.x + vB0.x*vB0.x;
            s[1] += vA0.y + vB0.y; qq[1] += vA0.y*vA0.y + vB0.y*vB0.y;
            s[2] += vA0.z + vB0.z; qq[2] += vA0.z*vA0.z + vB0.z*vB0.z;
            s[3] += vA0.w + vB0.w; qq[3] += vA0.w*vA0.w + vB0.w*vB0.w;
            s[4] += vA1.x + vB1.x; qq[4] += vA1.x*vA1.x + vB1.x*vB1.x;
            s[5] += vA1.y + vB1.y; qq[5] += vA1.y*vA1.y + vB1.y*vB1.y;
            s[6] += vA1.z + vB1.z; qq[6] += vA1.z*vA1.z + vB1.z*vB1.z;
            s[7] += vA1.w + vB1.w; qq[7] += vA1.w*vA1.w + vB1.w*vB1.w;

            uint4 w;
            w.x = pack8x4(vA0.x, vA0.y, vA0.z, vA0.w);
            w.y = pack8x4(vB0.x, vB0.y, vB0.z, vB0.w);
            w.z = pack8x4(vA1.x, vA1.y, vA1.z, vA1.w);
            w.w = pack8x4(vB1.x, vB1.y, vB1.z, vB1.w);
            xp4[wbase + (size_t)rr * 4] = w;
        }

        int c0 = g * 32 + qp * 4;
        *(float4*)(g_psum + (size_t)b * N_FEAT + c0)      = make_float4(s[0], s[1], s[2], s[3]);
        *(float4*)(g_psum + (size_t)b * N_FEAT + c0 + 16) = make_float4(s[4], s[5], s[6], s[7]);
        *(float4*)(g_psq  + (size_t)b * N_FEAT + c0)      = make_float4(qq[0], qq[1], qq[2], qq[3]);
        *(float4*)(g_psq  + (size_t)b * N_FEAT + c0 + 16) = make_float4(qq[4], qq[5], qq[6], qq[7]);
    } else {
        int i = (b - 1024) * 256 + threadIdx.x;
        g_tkey[i] = ~0ULL;
        g_tcnt[i] = 0u;
    }
}

// ---------------------------------------------------------------------------
// Kernel 2: finalize RunningMeanStd -> isig, mean*isig (FROZEN from R12).
// ---------------------------------------------------------------------------
__global__ void k_stats() {
    __shared__ float ss[32][8], sq[32][8];
    int c = threadIdx.x & 7, g = threadIdx.x >> 3;
    int col = blockIdx.x * 8 + c;
    float s = 0.f, q = 0.f;
#pragma unroll 4
    for (int st = g; st < NSTRIPE; st += 32) {
        s += g_psum[(size_t)st * N_FEAT + col];
        q += g_psq [(size_t)st * N_FEAT + col];
    }
    ss[g][c] = s; sq[g][c] = q;
    __syncthreads();
    if (g == 0) {
#pragma unroll
        for (int j = 1; j < 32; j++) { s += ss[j][c]; q += sq[j][c]; }
        const float n = 16384.0f;
        float bm = s / n;
        float bv = (q - bm * bm * n) / (n - 1.0f);       // unbiased variance
        const double nd = 16384.0, totd = 1e-4 + nd;
        float mean = bm * (float)(nd / totd);
        float m2v  = (1e-4f + bv * 16384.0f) + (bm * bm) * (float)(1e-4 * nd / totd);
        float var  = m2v / (float)totd;
        float isg  = 1.0f / sqrtf(var + 1e-8f);
        g_isig[col] = isg;
        g_m2[col]   = mean * isg;
    }
}

// ---------------------------------------------------------------------------
// Kernel 3: RP'' = 256*isig*RP packed e4m3x4 swizzled (blocks 0..63);
//           off[b] = 256 * sum_k m2[k]*RP[k,b] (block 64, deterministic).
// ---------------------------------------------------------------------------
__global__ void k_scale(const float* __restrict__ rp) {
    if (blockIdx.x < 64) {
        int idx = blockIdx.x * 256 + threadIdx.x;  // 0..16383
        int k4 = idx >> 5;                         // 4-col k word 0..511
        int n  = idx & 31;
        float f0 = rp[(4 * k4 + 0) * N_BINS + n] * g_isig[4 * k4 + 0] * 256.0f;
        float f1 = rp[(4 * k4 + 1) * N_BINS + n] * g_isig[4 * k4 + 1] * 256.0f;
        float f2 = rp[(4 * k4 + 2) * N_BINS + n] * g_isig[4 * k4 + 2] * 256.0f;
        float f3 = rp[(4 * k4 + 3) * N_BINS + n] * g_isig[4 * k4 + 3] * 256.0f;
        int scol = n ^ ((k4 & 3) << 3);
        g_rppack8[k4 * 32 + scol] = pack8x4(f0, f1, f2, f3);
    } else {
        __shared__ float red[8][32];
        int b = threadIdx.x & 31, part = threadIdx.x >> 5;   // 8 parts x 256 k
        float s = 0.f;
        for (int k = part * 256; k < part * 256 + 256; k++)
            s = fmaf(g_m2[k], rp[k * N_BINS + b], s);
        red[part][b] = s;
        __syncthreads();
        if (part == 0) {
#pragma unroll
            for (int j = 1; j < 8; j++) s += red[j][b];
            g_off[b] = s * 256.0f;
        }
    }
}

// ---------------------------------------------------------------------------
// Kernel 4: FULL-K e4m3 mma projection, one block per 128-row tile.
//   R13 structure; ONLY change: inner group loop is #pragma unroll 4
//   (was fully unrolled -> regs=255 -> spills). kq loop stays unrolled for
//   static buffer / wait_group selection.
// ---------------------------------------------------------------------------
__global__ void __launch_bounds__(256, 1) k_project() {
    extern __shared__ unsigned smem[];
    unsigned* srp = smem;                        // [0,16384) words: RP full
    unsigned* sa0 = smem + 16384;                // A buffer 0 (16384 words)
    unsigned* sa1 = smem + 32768;                // A buffer 1
    float* soff   = (float*)(smem + 49152);      // [32]

    int tile = blockIdx.x;
    int tid  = threadIdx.x;

    // stage RP full (4096 x 16B) + A chunk 0 -> group 0
    {
        const char* src = (const char*)g_rppack8;
        uint32_t dst = smaddr(srp);
#pragma unroll
        for (int i = 0; i < 16; i++) {
            int idx = tid + i * 256;
            cpa16(dst + idx * 16, src + idx * 16);
        }
    }
    {
        uint32_t dst = smaddr(sa0);
#pragma unroll
        for (int i = 0; i < 16; i++) {
            int idx = tid + i * 256;
            int w = idx >> 9, inner = idx & 511;
            const char* src = (const char*)g_xpack8 +
                (((size_t)(tile * 8 + w) * NG + 0 * 16) * 512 + (size_t)inner * 16);
            cpa16(dst + idx * 16, src);
        }
    }
    if (tid < 32) soff[tid] = g_off[tid];
    asm volatile("cp.async.commit_group;");
    {
        uint32_t dst = smaddr(sa1);
#pragma unroll
        for (int i = 0; i < 16; i++) {
            int idx = tid + i * 256;
            int w = idx >> 9, inner = idx & 511;
            const char* src = (const char*)g_xpack8 +
                (((size_t)(tile * 8 + w) * NG + 1 * 16) * 512 + (size_t)inner * 16);
            cpa16(dst + idx * 16, src);
        }
    }
    asm volatile("cp.async.commit_group;");

    int warp = tid >> 5, lane = tid & 31;
    int q = lane & 3, r = lane >> 2;
    int tile16 = tile * 8 + warp;
    int rowA = tile16 * 16 + r, rowB = rowA + 8;

    float acc[4][4];
#pragma unroll
    for (int t = 0; t < 4; t++)
#pragma unroll
        for (int c = 0; c < 4; c++) acc[t][c] = 0.f;

    unsigned scol[4];
#pragma unroll
    for (int t = 0; t < 4; t++) scol[t] = (unsigned)((t * 8 + r) ^ (q << 3));

#pragma unroll
    for (int kq = 0; kq < 4; kq++) {
        if (kq < 3) cpa_wait<1>(); else cpa_wait<0>();
        __syncthreads();

        unsigned* sa = (kq & 1) ? sa1 : sa0;
        const uint4* ap = (const uint4*)sa + warp * 512 + lane;
#pragma unroll 4
        for (int gg = 0; gg < 16; gg++) {            // 16 groups of 32 k-cols
            uint4 a = ap[gg * 32];                   // fragment regs (LDS.128)
            int g = kq * 16 + gg;
            int w0 = (g * 8 + q) * 32;
            int w1 = (g * 8 + q + 4) * 32;
#pragma unroll
            for (int t = 0; t < 4; t++) {
                unsigned b0 = srp[w0 + scol[t]];
                unsigned b1 = srp[w1 + scol[t]];
                mma16832(acc[t], a.x, a.y, a.z, a.w, b0, b1);
            }
        }
        __syncthreads();

        if (kq < 2) {    // stage chunk kq+2 into the buffer just freed
            unsigned* dstbuf = (kq & 1) ? sa1 : sa0;
            uint32_t dst = smaddr(dstbuf);
            int kn = kq + 2;
#pragma unroll
            for (int i = 0; i < 16; i++) {
                int idx = tid + i * 256;
                int w = idx >> 9, inner = idx & 511;
                const char* src = (const char*)g_xpack8 +
                    (((size_t)(tile * 8 + w) * NG + kn * 16) * 512 + (size_t)inner * 16);
                cpa16(dst + idx * 16, src);
            }
            asm volatile("cp.async.commit_group;");
        }
    }

    // full-K accumulators -> offset-subtract -> sign bits -> hash -> insert
    unsigned mlo = 0u, mhi = 0u;
#pragma unroll
    for (int t = 0; t < 4; t++) {
        int cb = t * 8 + 2 * q;
        float o0 = soff[cb], o1 = soff[cb + 1];
        mlo |= ((acc[t][0] - o0) > 0.f ? 1u : 0u) << cb;
        mlo |= ((acc[t][1] - o1) > 0.f ? 1u : 0u) << (cb + 1);
        mhi |= ((acc[t][2] - o0) > 0.f ? 1u : 0u) << cb;
        mhi |= ((acc[t][3] - o1) > 0.f ? 1u : 0u) << (cb + 1);
    }
    mlo |= __shfl_xor_sync(0xffffffffu, mlo, 1);
    mlo |= __shfl_xor_sync(0xffffffffu, mlo, 2);
    mhi |= __shfl_xor_sync(0xffffffffu, mhi, 1);
    mhi |= __shfl_xor_sync(0xffffffffu, mhi, 2);

    if (q == 0) {
        g_hash[rowA] = mlo;
        g_hash[rowB] = mhi;
        table_insert(rowA, mlo);
        table_insert(rowB, mhi);
    }
}

// ---------------------------------------------------------------------------
// Kernel 5: rewards. Unique keys -> 1.0; rare duplicates get exact rank.
// ---------------------------------------------------------------------------
__global__ void k_final(float* __restrict__ out) {
    int i = blockIdx.x * 256 + threadIdx.x;
    unsigned s = g_slot[i];
    float v = 1.0f;
    if (g_tcnt[s] != 1u) {
        unsigned long long my = ((unsigned long long)g_hash[i] << 6) | (unsigned long long)(i & 63);
        int c = 1;
        for (int j = 0; j < i; j++) {
            unsigned long long kj = ((unsigned long long)g_hash[j] << 6) | (unsigned long long)(j & 63);
            c += (kj == my) ? 1 : 0;
        }
        v = 1.0f / sqrtf((float)c);
    }
    out[i] = v;
}

// ---------------------------------------------------------------------------
// Launch (5 launches; 4th = k_project gets the ncu profile)
// ---------------------------------------------------------------------------
extern "C" void kernel_launch(void* const* d_in, const int* in_sizes, int n_in,
                              void* d_out, int out_size) {
    const float* x  = (const float*)d_in[0];
    const float* rp = (const float*)d_in[1];
    if (in_sizes[0] == N_FEAT * N_BINS) {   // defensive: swap if order differs
        const float* t = x; x = rp; rp = t;
    }
    float* out = (float*)d_out;

    cudaFuncSetAttribute(k_project, cudaFuncAttributeMaxDynamicSharedMemorySize, PROJ_SMEM);

    k_pre    <<<1280, 256>>>(x);
    k_stats  <<<256, 256>>>();
    k_scale  <<<65, 256>>>(rp);
    k_project<<<NTILE, 256, PROJ_SMEM>>>();
    k_final  <<<64, 256>>>(out);
}

// round 16
// speedup vs baseline: 1.6025x; 1.0561x over previous
#include <cuda_runtime.h>
#include <cstdint>

// ---------------------------------------------------------------------------
// Problem constants
// ---------------------------------------------------------------------------
#define N_ROWS 16384      // 64 * 256
#define N_FEAT 2048
#define N_BINS 32
#define NSTRIPE 1024               // one stripe per 16-row tile
#define TBL 65536
#define NTILE 128                  // 128-row tiles
#define NG 64                      // 32-col groups over full K
#define NT16 (N_ROWS / 16)         // 1024 16-row fragments
// k_project dynamic smem: RP full 64KB + 2 x 64KB A chunk buffers + soff
#define PROJ_SMEM (65536 * 3 + 128)   // 196736
#define OFF_SCALE 1099511627776.0f    // 2^40 fixed-point scale for offsets

// ---------------------------------------------------------------------------
// Scratch (static device globals; no runtime allocation)
// ---------------------------------------------------------------------------
__device__ __align__(16) unsigned int g_xpack8[(size_t)NT16 * NG * 32 * 4]; // e4m3 x (32MB)
__device__ float              g_psum[(size_t)NSTRIPE * N_FEAT];   // 8MB
__device__ float              g_psq [(size_t)NSTRIPE * N_FEAT];   // 8MB
__device__ unsigned long long g_ioff[N_BINS];    // fixed-point 256*(m2.RP)
__device__ __align__(16) unsigned int g_rppack8[512 * 32]; // e4m3x4 256*isig*RP, swizzled
__device__ unsigned int       g_hash[N_ROWS];
__device__ unsigned int       g_slot[N_ROWS];
__device__ unsigned long long g_tkey[TBL];
__device__ unsigned int       g_tcnt[TBL];

// ---------------------------------------------------------------------------
// Helpers
// ---------------------------------------------------------------------------
__device__ __forceinline__ unsigned pack8x4(float f0, float f1, float f2, float f3) {
    unsigned d;
    asm("{\n\t"
        ".reg .b16 lo, hi;\n\t"
        "cvt.rn.satfinite.e4m3x2.f32 lo, %2, %1;\n\t"
        "cvt.rn.satfinite.e4m3x2.f32 hi, %4, %3;\n\t"
        "mov.b32 %0, {lo, hi};\n\t"
        "}" : "=r"(d) : "f"(f0), "f"(f1), "f"(f2), "f"(f3));
    return d;
}

__device__ __forceinline__ void mma16832(float* c,
                                         unsigned a0, unsigned a1, unsigned a2, unsigned a3,
                                         unsigned b0, unsigned b1) {
    asm volatile(
        "mma.sync.aligned.m16n8k32.row.col.f32.e4m3.e4m3.f32 "
        "{%0,%1,%2,%3}, {%4,%5,%6,%7}, {%8,%9}, {%0,%1,%2,%3};"
        : "+f"(c[0]), "+f"(c[1]), "+f"(c[2]), "+f"(c[3])
        : "r"(a0), "r"(a1), "r"(a2), "r"(a3), "r"(b0), "r"(b1));
}

__device__ __forceinline__ uint32_t smaddr(const void* p) {
    return (uint32_t)__cvta_generic_to_shared(p);
}

__device__ __forceinline__ void cpa16(uint32_t dst, const void* src) {
    asm volatile("cp.async.cg.shared.global [%0], [%1], 16;" :: "r"(dst), "l"(src));
}

template<int N> __device__ __forceinline__ void cpa_wait() {
    asm volatile("cp.async.wait_group %0;" :: "n"(N) : "memory");
}

__device__ __forceinline__ void table_insert(int i, unsigned h) {
    unsigned long long key = ((unsigned long long)h << 6) | (unsigned long long)(i & 63);
    unsigned long long m = key * 0x9E3779B97F4A7C15ULL;
    unsigned s = (unsigned)(m >> 48);   // 16-bit slot
    for (;;) {
        unsigned long long prev = atomicCAS(&g_tkey[s], ~0ULL, key);
        if (prev == ~0ULL || prev == key) {
            atomicAdd(&g_tcnt[s], 1u);
            g_slot[i] = s;
            return;
        }
        s = (s + 1) & (TBL - 1);
    }
}

// ---------------------------------------------------------------------------
// Kernel 1 (fused): column partial sums + e4m3 fragment pack + table inits.
//   blocks [0,1024): one per tile16 (FROZEN since R11, measured 28.4us).
//   blocks [1024,1280): hash-table init + g_ioff zero.
// ---------------------------------------------------------------------------
__global__ void __launch_bounds__(256, 4) k_pre(const float* __restrict__ x) {
    int b = blockIdx.x;
    if (b < 1024) {
        int tid = threadIdx.x;
        int g = tid >> 2, qp = tid & 3;
        int f0 = g * 8 + qp;                // float4 slot, khalf=0
        int f1 = f0 + 4;                    // float4 slot, khalf=1
        const float4* x4 = (const float4*)x;
        uint4* xp4 = (uint4*)g_xpack8;

        size_t rbase = (size_t)b * 16 * 512;               // float4 units
        size_t wbase = ((size_t)b * NG + g) * 32 + qp;     // uint4 units

        float s[8], qq[8];
#pragma unroll
        for (int j = 0; j < 8; j++) { s[j] = 0.f; qq[j] = 0.f; }

#pragma unroll 2
        for (int rr = 0; rr < 8; rr++) {
            size_t rA = rbase + (size_t)rr * 512;
            size_t rB = rA + 8 * 512;
            float4 vA0 = x4[rA + f0];
            float4 vA1 = x4[rA + f1];
            float4 vB0 = x4[rB + f0];
            float4 vB1 = x4[rB + f1];

            s[0] += vA0.x + vB0.x; qq[0] += vA0.x*vA0.x + vB0.x*vB0.x;
            s[1] += vA0.y + vB0.y; qq[1] += vA0.y*vA0.y + vB0.y*vB0.y;
            s[2] += vA0.z + vB0.z; qq[2] += vA0.z*vA0.z + vB0.z*vB0.z;
            s[3] += vA0.w + vB0.w; qq[3] += vA0.w*vA0.w + vB0.w*vB0.w;
            s[4] += vA1.x + vB1.x; qq[4] += vA1.x*vA1.x + vB1.x*vB1.x;
            s[5] += vA1.y + vB1.y; qq[5] += vA1.y*vA1.y + vB1.y*vB1.y;
            s[6] += vA1.z + vB1.z; qq[6] += vA1.z*vA1.z + vB1.z*vB1.z;
            s[7] += vA1.w + vB1.w; qq[7] += vA1.w*vA1.w + vB1.w*vB1.w;

            uint4 w;
            w.x = pack8x4(vA0.x, vA0.y, vA0.z, vA0.w);
            w.y = pack8x4(vB0.x, vB0.y, vB0.z, vB0.w);
            w.z = pack8x4(vA1.x, vA1.y, vA1.z, vA1.w);
            w.w = pack8x4(vB1.x, vB1.y, vB1.z, vB1.w);
            xp4[wbase + (size_t)rr * 4] = w;
        }

        int c0 = g * 32 + qp * 4;
        *(float4*)(g_psum + (size_t)b * N_FEAT + c0)      = make_float4(s[0], s[1], s[2], s[3]);
        *(float4*)(g_psum + (size_t)b * N_FEAT + c0 + 16) = make_float4(s[4], s[5], s[6], s[7]);
        *(float4*)(g_psq  + (size_t)b * N_FEAT + c0)      = make_float4(qq[0], qq[1], qq[2], qq[3]);
        *(float4*)(g_psq  + (size_t)b * N_FEAT + c0 + 16) = make_float4(qq[4], qq[5], qq[6], qq[7]);
    } else {
        int i = (b - 1024) * 256 + threadIdx.x;
        g_tkey[i] = ~0ULL;
        g_tcnt[i] = 0u;
        if (b == 1024 && threadIdx.x < N_BINS) g_ioff[threadIdx.x] = 0ull;
    }
}

// ---------------------------------------------------------------------------
// Kernel 2 (fused stats+scale, NO device sync): 64 blocks x 256.
//   Block bb owns k-columns [bb*32, bb*32+32) == k4 words [bb*8, bb*8+8).
//   Phase 1: reduce psum/psq over 1024 stripes for these 32 cols -> isig, m2.
//   Phase 2: pack RP'' = 256*isig*RP (e4m3x4, swizzled) for its 8 k4-words.
//   Phase 3: offset partial: sum_k m2[k]*RP[k,n] over its 32 k, fixed-point
//            atomicAdd to g_ioff[n] (integer -> order-independent).
// ---------------------------------------------------------------------------
__global__ void k_scale(const float* __restrict__ rp) {
    __shared__ float red[8][32];
    __shared__ float redq[8][32];
    __shared__ float s_isig[32], s_m2[32];

    int bb = blockIdx.x;                    // 0..63
    int c  = threadIdx.x & 31;              // local column / bin index
    int gp = threadIdx.x >> 5;              // 0..7
    int col = bb * 32 + c;

    // Phase 1: column stats for this block's 32 columns
    float s = 0.f, q = 0.f;
#pragma unroll 8
    for (int st = gp; st < NSTRIPE; st += 8) {
        s += g_psum[(size_t)st * N_FEAT + col];
        q += g_psq [(size_t)st * N_FEAT + col];
    }
    red[gp][c] = s; redq[gp][c] = q;
    __syncthreads();
    if (gp == 0) {
#pragma unroll
        for (int j = 1; j < 8; j++) { s += red[j][c]; q += redq[j][c]; }
        const float n = 16384.0f;
        float bm = s / n;
        float bv = (q - bm * bm * n) / (n - 1.0f);       // unbiased variance
        const double nd = 16384.0, totd = 1e-4 + nd;
        float mean = bm * (float)(nd / totd);
        float m2v  = (1e-4f + bv * 16384.0f) + (bm * bm) * (float)(1e-4 * nd / totd);
        float var  = m2v / (float)totd;
        float isg  = 1.0f / sqrtf(var + 1e-8f);
        s_isig[c] = isg;
        s_m2[c]   = mean * isg;
    }
    __syncthreads();

    // Phase 2: RP'' pack for this block's 8 k4-words (256 threads = 8x32)
    int k4l = gp;                           // local k4 word 0..7
    int k4  = bb * 8 + k4l;
    float r0 = rp[(4 * k4 + 0) * N_BINS + c];
    float r1 = rp[(4 * k4 + 1) * N_BINS + c];
    float r2 = rp[(4 * k4 + 2) * N_BINS + c];
    float r3 = rp[(4 * k4 + 3) * N_BINS + c];
    {
        float f0 = r0 * s_isig[k4l * 4 + 0] * 256.0f;
        float f1 = r1 * s_isig[k4l * 4 + 1] * 256.0f;
        float f2 = r2 * s_isig[k4l * 4 + 2] * 256.0f;
        float f3 = r3 * s_isig[k4l * 4 + 3] * 256.0f;
        int scol = c ^ ((k4 & 3) << 3);
        g_rppack8[k4 * 32 + scol] = pack8x4(f0, f1, f2, f3);
    }

    // Phase 3: offset partial for this block's 32 k-columns
    float p = s_m2[k4l * 4 + 0] * r0
            + s_m2[k4l * 4 + 1] * r1
            + s_m2[k4l * 4 + 2] * r2
            + s_m2[k4l * 4 + 3] * r3;
    __syncthreads();                        // red[] reuse
    red[gp][c] = p;
    __syncthreads();
    if (gp == 0) {
#pragma unroll
        for (int j = 1; j < 8; j++) p += red[j][c];
        long long fx = llrintf(p * 256.0f * OFF_SCALE);
        atomicAdd(&g_ioff[c], (unsigned long long)fx);
    }
}

// ---------------------------------------------------------------------------
// Kernel 3: FULL-K e4m3 mma projection (core FROZEN from R15, 20.1us).
//   Only change: soff loaded from fixed-point g_ioff.
// ---------------------------------------------------------------------------
__global__ void __launch_bounds__(256, 1) k_project() {
    extern __shared__ unsigned smem[];
    unsigned* srp = smem;                        // [0,16384) words: RP full
    unsigned* sa0 = smem + 16384;                // A buffer 0 (16384 words)
    unsigned* sa1 = smem + 32768;                // A buffer 1
    float* soff   = (float*)(smem + 49152);      // [32]

    int tile = blockIdx.x;
    int tid  = threadIdx.x;

    // stage RP full (4096 x 16B) + A chunk 0 -> group 0
    {
        const char* src = (const char*)g_rppack8;
        uint32_t dst = smaddr(srp);
#pragma unroll
        for (int i = 0; i < 16; i++) {
            int idx = tid + i * 256;
            cpa16(dst + idx * 16, src + idx * 16);
        }
    }
    {
        uint32_t dst = smaddr(sa0);
#pragma unroll
        for (int i = 0; i < 16; i++) {
            int idx = tid + i * 256;
            int w = idx >> 9, inner = idx & 511;
            const char* src = (const char*)g_xpack8 +
                (((size_t)(tile * 8 + w) * NG + 0 * 16) * 512 + (size_t)inner * 16);
            cpa16(dst + idx * 16, src);
        }
    }
    if (tid < 32)
        soff[tid] = (float)(long long)g_ioff[tid] * (1.0f / OFF_SCALE);
    asm volatile("cp.async.commit_group;");
    {
        uint32_t dst = smaddr(sa1);
#pragma unroll
        for (int i = 0; i < 16; i++) {
            int idx = tid + i * 256;
            int w = idx >> 9, inner = idx & 511;
            const char* src = (const char*)g_xpack8 +
                (((size_t)(tile * 8 + w) * NG + 1 * 16) * 512 + (size_t)inner * 16);
            cpa16(dst + idx * 16, src);
        }
    }
    asm volatile("cp.async.commit_group;");

    int warp = tid >> 5, lane = tid & 31;
    int q = lane & 3, r = lane >> 2;
    int tile16 = tile * 8 + warp;
    int rowA = tile16 * 16 + r, rowB = rowA + 8;

    float acc[4][4];
#pragma unroll
    for (int t = 0; t < 4; t++)
#pragma unroll
        for (int c = 0; c < 4; c++) acc[t][c] = 0.f;

    unsigned scol[4];
#pragma unroll
    for (int t = 0; t < 4; t++) scol[t] = (unsigned)((t * 8 + r) ^ (q << 3));

#pragma unroll
    for (int kq = 0; kq < 4; kq++) {
        if (kq < 3) cpa_wait<1>(); else cpa_wait<0>();
        __syncthreads();

        unsigned* sa = (kq & 1) ? sa1 : sa0;
        const uint4* ap = (const uint4*)sa + warp * 512 + lane;
#pragma unroll 4
        for (int gg = 0; gg < 16; gg++) {            // 16 groups of 32 k-cols
            uint4 a = ap[gg * 32];                   // fragment regs (LDS.128)
            int g = kq * 16 + gg;
            int w0 = (g * 8 + q) * 32;
            int w1 = (g * 8 + q + 4) * 32;
#pragma unroll
            for (int t = 0; t < 4; t++) {
                unsigned b0 = srp[w0 + scol[t]];
                unsigned b1 = srp[w1 + scol[t]];
                mma16832(acc[t], a.x, a.y, a.z, a.w, b0, b1);
            }
        }
        __syncthreads();

        if (kq < 2) {    // stage chunk kq+2 into the buffer just freed
            unsigned* dstbuf = (kq & 1) ? sa1 : sa0;
            uint32_t dst = smaddr(dstbuf);
            int kn = kq + 2;
#pragma unroll
            for (int i = 0; i < 16; i++) {
                int idx = tid + i * 256;
                int w = idx >> 9, inner = idx & 511;
                const char* src = (const char*)g_xpack8 +
                    (((size_t)(tile * 8 + w) * NG + kn * 16) * 512 + (size_t)inner * 16);
                cpa16(dst + idx * 16, src);
            }
            asm volatile("cp.async.commit_group;");
        }
    }

    // full-K accumulators -> offset-subtract -> sign bits -> hash -> insert
    unsigned mlo = 0u, mhi = 0u;
#pragma unroll
    for (int t = 0; t < 4; t++) {
        int cb = t * 8 + 2 * q;
        float o0 = soff[cb], o1 = soff[cb + 1];
        mlo |= ((acc[t][0] - o0) > 0.f ? 1u : 0u) << cb;
        mlo |= ((acc[t][1] - o1) > 0.f ? 1u : 0u) << (cb + 1);
        mhi |= ((acc[t][2] - o0) > 0.f ? 1u : 0u) << cb;
        mhi |= ((acc[t][3] - o1) > 0.f ? 1u : 0u) << (cb + 1);
    }
    mlo |= __shfl_xor_sync(0xffffffffu, mlo, 1);
    mlo |= __shfl_xor_sync(0xffffffffu, mlo, 2);
    mhi |= __shfl_xor_sync(0xffffffffu, mhi, 1);
    mhi |= __shfl_xor_sync(0xffffffffu, mhi, 2);

    if (q == 0) {
        g_hash[rowA] = mlo;
        g_hash[rowB] = mhi;
        table_insert(rowA, mlo);
        table_insert(rowB, mhi);
    }
}

// ---------------------------------------------------------------------------
// Kernel 4: rewards. Unique keys -> 1.0; rare duplicates get exact rank.
// ---------------------------------------------------------------------------
__global__ void k_final(float* __restrict__ out) {
    int i = blockIdx.x * 256 + threadIdx.x;
    unsigned s = g_slot[i];
    float v = 1.0f;
    if (g_tcnt[s] != 1u) {
        unsigned long long my = ((unsigned long long)g_hash[i] << 6) | (unsigned long long)(i & 63);
        int c = 1;
        for (int j = 0; j < i; j++) {
            unsigned long long kj = ((unsigned long long)g_hash[j] << 6) | (unsigned long long)(j & 63);
            c += (kj == my) ? 1 : 0;
        }
        v = 1.0f / sqrtf((float)c);
    }
    out[i] = v;
}

// ---------------------------------------------------------------------------
// Launch (4 launches)
// ---------------------------------------------------------------------------
extern "C" void kernel_launch(void* const* d_in, const int* in_sizes, int n_in,
                              void* d_out, int out_size) {
    const float* x  = (const float*)d_in[0];
    const float* rp = (const float*)d_in[1];
    if (in_sizes[0] == N_FEAT * N_BINS) {   // defensive: swap if order differs
        const float* t = x; x = rp; rp = t;
    }
    float* out = (float*)d_out;

    cudaFuncSetAttribute(k_project, cudaFuncAttributeMaxDynamicSharedMemorySize, PROJ_SMEM);

    k_pre    <<<1280, 256>>>(x);
    k_scale  <<<64, 256>>>(rp);
    k_project<<<NTILE, 256, PROJ_SMEM>>>();
    k_final  <<<64, 256>>>(out);
}

// round 17
// speedup vs baseline: 1.6086x; 1.0038x over previous
#include <cuda_runtime.h>
#include <cstdint>

// ---------------------------------------------------------------------------
// Problem constants
// ---------------------------------------------------------------------------
#define N_ROWS 16384      // 64 * 256
#define N_FEAT 2048
#define N_BINS 32
#define NSTRIPE 1024               // one stripe per 16-row tile
#define TBL 65536
#define NTILE 128                  // 128-row tiles
#define NG 64                      // 32-col groups over full K
#define NT16 (N_ROWS / 16)         // 1024 16-row fragments
// k_project dynamic smem: RP full 64KB + 2 x 64KB A chunk buffers + soff
#define PROJ_SMEM (65536 * 3 + 128)   // 196736
#define OFF_SCALE 1099511627776.0f    // 2^40 fixed-point scale for offsets

// ---------------------------------------------------------------------------
// Scratch (static device globals; no runtime allocation)
// ---------------------------------------------------------------------------
__device__ __align__(16) unsigned int g_xpack8[(size_t)NT16 * NG * 32 * 4]; // e4m3 x (32MB)
__device__ float              g_psum[(size_t)NSTRIPE * N_FEAT];   // 8MB
__device__ float              g_psq [(size_t)NSTRIPE * N_FEAT];   // 8MB
__device__ unsigned long long g_ioff[N_BINS];    // fixed-point 256*(m2.RP)
__device__ __align__(16) unsigned int g_rppack8[512 * 32]; // e4m3x4 256*isig*RP, swizzled
__device__ unsigned int       g_hash[N_ROWS];
__device__ unsigned int       g_slot[N_ROWS];
__device__ unsigned long long g_tkey[TBL];
__device__ unsigned int       g_tcnt[TBL];

// ---------------------------------------------------------------------------
// Helpers
// ---------------------------------------------------------------------------
__device__ __forceinline__ unsigned pack8x4(float f0, float f1, float f2, float f3) {
    unsigned d;
    asm("{\n\t"
        ".reg .b16 lo, hi;\n\t"
        "cvt.rn.satfinite.e4m3x2.f32 lo, %2, %1;\n\t"
        "cvt.rn.satfinite.e4m3x2.f32 hi, %4, %3;\n\t"
        "mov.b32 %0, {lo, hi};\n\t"
        "}" : "=r"(d) : "f"(f0), "f"(f1), "f"(f2), "f"(f3));
    return d;
}

__device__ __forceinline__ void mma16832(float* c,
                                         unsigned a0, unsigned a1, unsigned a2, unsigned a3,
                                         unsigned b0, unsigned b1) {
    asm volatile(
        "mma.sync.aligned.m16n8k32.row.col.f32.e4m3.e4m3.f32 "
        "{%0,%1,%2,%3}, {%4,%5,%6,%7}, {%8,%9}, {%0,%1,%2,%3};"
        : "+f"(c[0]), "+f"(c[1]), "+f"(c[2]), "+f"(c[3])
        : "r"(a0), "r"(a1), "r"(a2), "r"(a3), "r"(b0), "r"(b1));
}

__device__ __forceinline__ uint32_t smaddr(const void* p) {
    return (uint32_t)__cvta_generic_to_shared(p);
}

__device__ __forceinline__ void cpa16(uint32_t dst, const void* src) {
    asm volatile("cp.async.cg.shared.global [%0], [%1], 16;" :: "r"(dst), "l"(src));
}

template<int N> __device__ __forceinline__ void cpa_wait() {
    asm volatile("cp.async.wait_group %0;" :: "n"(N) : "memory");
}

__device__ __forceinline__ void table_insert(int i, unsigned h) {
    unsigned long long key = ((unsigned long long)h << 6) | (unsigned long long)(i & 63);
    unsigned long long m = key * 0x9E3779B97F4A7C15ULL;
    unsigned s = (unsigned)(m >> 48);   // 16-bit slot
    for (;;) {
        unsigned long long prev = atomicCAS(&g_tkey[s], ~0ULL, key);
        if (prev == ~0ULL || prev == key) {
            atomicAdd(&g_tcnt[s], 1u);
            g_slot[i] = s;
            return;
        }
        s = (s + 1) & (TBL - 1);
    }
}

// ---------------------------------------------------------------------------
// Kernel 1 (fused): column partial sums + e4m3 fragment pack + table inits.
//   blocks [0,1024): one per tile16 (FROZEN since R11, measured 28.4us).
//   blocks [1024,1280): hash-table init + g_ioff zero.
// ---------------------------------------------------------------------------
__global__ void __launch_bounds__(256, 4) k_pre(const float* __restrict__ x) {
    int b = blockIdx.x;
    if (b < 1024) {
        int tid = threadIdx.x;
        int g = tid >> 2, qp = tid & 3;
        int f0 = g * 8 + qp;                // float4 slot, khalf=0
        int f1 = f0 + 4;                    // float4 slot, khalf=1
        const float4* x4 = (const float4*)x;
        uint4* xp4 = (uint4*)g_xpack8;

        size_t rbase = (size_t)b * 16 * 512;               // float4 units
        size_t wbase = ((size_t)b * NG + g) * 32 + qp;     // uint4 units

        float s[8], qq[8];
#pragma unroll
        for (int j = 0; j < 8; j++) { s[j] = 0.f; qq[j] = 0.f; }

#pragma unroll 2
        for (int rr = 0; rr < 8; rr++) {
            size_t rA = rbase + (size_t)rr * 512;
            size_t rB = rA + 8 * 512;
            float4 vA0 = x4[rA + f0];
            float4 vA1 = x4[rA + f1];
            float4 vB0 = x4[rB + f0];
            float4 vB1 = x4[rB + f1];

            s[0] += vA0.x + vB0.x; qq[0] += vA0.x*vA0.x + vB0.x*vB0.x;
            s[1] += vA0.y + vB0.y; qq[1] += vA0.y*vA0.y + vB0.y*vB0.y;
            s[2] += vA0.z + vB0.z; qq[2] += vA0.z*vA0.z + vB0.z*vB0.z;
            s[3] += vA0.w + vB0.w; qq[3] += vA0.w*vA0.w + vB0.w*vB0.w;
            s[4] += vA1.x + vB1.x; qq[4] += vA1.x*vA1.x + vB1.x*vB1.x;
            s[5] += vA1.y + vB1.y; qq[5] += vA1.y*vA1.y + vB1.y*vB1.y;
            s[6] += vA1.z + vB1.z; qq[6] += vA1.z*vA1.z + vB1.z*vB1.z;
            s[7] += vA1.w + vB1.w; qq[7] += vA1.w*vA1.w + vB1.w*vB1.w;

            uint4 w;
            w.x = pack8x4(vA0.x, vA0.y, vA0.z, vA0.w);
            w.y = pack8x4(vB0.x, vB0.y, vB0.z, vB0.w);
            w.z = pack8x4(vA1.x, vA1.y, vA1.z, vA1.w);
            w.w = pack8x4(vB1.x, vB1.y, vB1.z, vB1.w);
            xp4[wbase + (size_t)rr * 4] = w;
        }

        int c0 = g * 32 + qp * 4;
        *(float4*)(g_psum + (size_t)b * N_FEAT + c0)      = make_float4(s[0], s[1], s[2], s[3]);
        *(float4*)(g_psum + (size_t)b * N_FEAT + c0 + 16) = make_float4(s[4], s[5], s[6], s[7]);
        *(float4*)(g_psq  + (size_t)b * N_FEAT + c0)      = make_float4(qq[0], qq[1], qq[2], qq[3]);
        *(float4*)(g_psq  + (size_t)b * N_FEAT + c0 + 16) = make_float4(qq[4], qq[5], qq[6], qq[7]);
    } else {
        int i = (b - 1024) * 256 + threadIdx.x;
        g_tkey[i] = ~0ULL;
        g_tcnt[i] = 0u;
        if (b == 1024 && threadIdx.x < N_BINS) g_ioff[threadIdx.x] = 0ull;
    }
}

// ---------------------------------------------------------------------------
// Kernel 2 (fused stats+scale, FROZEN from R16): 64 blocks x 256.
// ---------------------------------------------------------------------------
__global__ void k_scale(const float* __restrict__ rp) {
    __shared__ float red[8][32];
    __shared__ float redq[8][32];
    __shared__ float s_isig[32], s_m2[32];

    int bb = blockIdx.x;                    // 0..63
    int c  = threadIdx.x & 31;              // local column / bin index
    int gp = threadIdx.x >> 5;              // 0..7
    int col = bb * 32 + c;

    float s = 0.f, q = 0.f;
#pragma unroll 8
    for (int st = gp; st < NSTRIPE; st += 8) {
        s += g_psum[(size_t)st * N_FEAT + col];
        q += g_psq [(size_t)st * N_FEAT + col];
    }
    red[gp][c] = s; redq[gp][c] = q;
    __syncthreads();
    if (gp == 0) {
#pragma unroll
        for (int j = 1; j < 8; j++) { s += red[j][c]; q += redq[j][c]; }
        const float n = 16384.0f;
        float bm = s / n;
        float bv = (q - bm * bm * n) / (n - 1.0f);       // unbiased variance
        const double nd = 16384.0, totd = 1e-4 + nd;
        float mean = bm * (float)(nd / totd);
        float m2v  = (1e-4f + bv * 16384.0f) + (bm * bm) * (float)(1e-4 * nd / totd);
        float var  = m2v / (float)totd;
        float isg  = 1.0f / sqrtf(var + 1e-8f);
        s_isig[c] = isg;
        s_m2[c]   = mean * isg;
    }
    __syncthreads();

    int k4l = gp;                           // local k4 word 0..7
    int k4  = bb * 8 + k4l;
    float r0 = rp[(4 * k4 + 0) * N_BINS + c];
    float r1 = rp[(4 * k4 + 1) * N_BINS + c];
    float r2 = rp[(4 * k4 + 2) * N_BINS + c];
    float r3 = rp[(4 * k4 + 3) * N_BINS + c];
    {
        float f0 = r0 * s_isig[k4l * 4 + 0] * 256.0f;
        float f1 = r1 * s_isig[k4l * 4 + 1] * 256.0f;
        float f2 = r2 * s_isig[k4l * 4 + 2] * 256.0f;
        float f3 = r3 * s_isig[k4l * 4 + 3] * 256.0f;
        int scol = c ^ ((k4 & 3) << 3);
        g_rppack8[k4 * 32 + scol] = pack8x4(f0, f1, f2, f3);
    }

    float p = s_m2[k4l * 4 + 0] * r0
            + s_m2[k4l * 4 + 1] * r1
            + s_m2[k4l * 4 + 2] * r2
            + s_m2[k4l * 4 + 3] * r3;
    __syncthreads();
    red[gp][c] = p;
    __syncthreads();
    if (gp == 0) {
#pragma unroll
        for (int j = 1; j < 8; j++) p += red[j][c];
        long long fx = llrintf(p * 256.0f * OFF_SCALE);
        atomicAdd(&g_ioff[c], (unsigned long long)fx);
    }
}

// ---------------------------------------------------------------------------
// Kernel 3: FULL-K e4m3 mma projection, 512 threads (16 warps):
//   warps 0-7 handle groups 0-7 of each chunk for their tile16;
//   warps 8-15 handle groups 8-15 of the SAME tile16.
//   After mainloop, high warps publish partial accs via smem (sa0 reuse),
//   low warps add and run sign/hash/insert.
// ---------------------------------------------------------------------------
__global__ void __launch_bounds__(512, 1) k_project() {
    extern __shared__ unsigned smem[];
    unsigned* srp = smem;                        // [0,16384) words: RP full
    unsigned* sa0 = smem + 16384;                // A buffer 0 (16384 words)
    unsigned* sa1 = smem + 32768;                // A buffer 1
    float* soff   = (float*)(smem + 49152);      // [32]

    int tile = blockIdx.x;
    int tid  = threadIdx.x;

    // stage RP full (4096 x 16B) + A chunk 0 -> group 0
    {
        const char* src = (const char*)g_rppack8;
        uint32_t dst = smaddr(srp);
#pragma unroll
        for (int i = 0; i < 8; i++) {
            int idx = tid + i * 512;
            cpa16(dst + idx * 16, src + idx * 16);
        }
    }
    {
        uint32_t dst = smaddr(sa0);
#pragma unroll
        for (int i = 0; i < 8; i++) {
            int idx = tid + i * 512;
            int w = idx >> 9, inner = idx & 511;
            const char* src = (const char*)g_xpack8 +
                (((size_t)(tile * 8 + w) * NG + 0 * 16) * 512 + (size_t)inner * 16);
            cpa16(dst + idx * 16, src);
        }
    }
    if (tid < 32)
        soff[tid] = (float)(long long)g_ioff[tid] * (1.0f / OFF_SCALE);
    asm volatile("cp.async.commit_group;");
    {
        uint32_t dst = smaddr(sa1);
#pragma unroll
        for (int i = 0; i < 8; i++) {
            int idx = tid + i * 512;
            int w = idx >> 9, inner = idx & 511;
            const char* src = (const char*)g_xpack8 +
                (((size_t)(tile * 8 + w) * NG + 1 * 16) * 512 + (size_t)inner * 16);
            cpa16(dst + idx * 16, src);
        }
    }
    asm volatile("cp.async.commit_group;");

    int warp = tid >> 5, lane = tid & 31;
    int wl = warp & 7;                    // tile16 slot within block
    int wh = warp >> 3;                   // 0: groups 0-7, 1: groups 8-15
    int q = lane & 3, r = lane >> 2;
    int tile16 = tile * 8 + wl;
    int rowA = tile16 * 16 + r, rowB = rowA + 8;

    float acc[4][4];
#pragma unroll
    for (int t = 0; t < 4; t++)
#pragma unroll
        for (int c = 0; c < 4; c++) acc[t][c] = 0.f;

    unsigned scol[4];
#pragma unroll
    for (int t = 0; t < 4; t++) scol[t] = (unsigned)((t * 8 + r) ^ (q << 3));

#pragma unroll
    for (int kq = 0; kq < 4; kq++) {
        if (kq < 3) cpa_wait<1>(); else cpa_wait<0>();
        __syncthreads();

        unsigned* sa = (kq & 1) ? sa1 : sa0;
        const uint4* ap = (const uint4*)sa + wl * 512 + wh * 256 + lane;
#pragma unroll 4
        for (int gg = 0; gg < 8; gg++) {             // my half: 8 groups
            uint4 a = ap[gg * 32];                   // fragment regs (LDS.128)
            int g = kq * 16 + wh * 8 + gg;
            int w0 = (g * 8 + q) * 32;
            int w1 = (g * 8 + q + 4) * 32;
#pragma unroll
            for (int t = 0; t < 4; t++) {
                unsigned b0 = srp[w0 + scol[t]];
                unsigned b1 = srp[w1 + scol[t]];
                mma16832(acc[t], a.x, a.y, a.z, a.w, b0, b1);
            }
        }
        __syncthreads();

        if (kq < 2) {    // stage chunk kq+2 into the buffer just freed
            unsigned* dstbuf = (kq & 1) ? sa1 : sa0;
            uint32_t dst = smaddr(dstbuf);
            int kn = kq + 2;
#pragma unroll
            for (int i = 0; i < 8; i++) {
                int idx = tid + i * 512;
                int w = idx >> 9, inner = idx & 511;
                const char* src = (const char*)g_xpack8 +
                    (((size_t)(tile * 8 + w) * NG + kn * 16) * 512 + (size_t)inner * 16);
                cpa16(dst + idx * 16, src);
            }
            asm volatile("cp.async.commit_group;");
        }
    }

    // combine warp-pair partials via smem (sa0 is dead now)
    float* xch = (float*)sa0;             // 8 warps * 32 lanes * 16 floats
    __syncthreads();
    if (wh == 1) {
        float4* dst = (float4*)(xch + (wl * 32 + lane) * 16);
#pragma unroll
        for (int t = 0; t < 4; t++)
            dst[t] = make_float4(acc[t][0], acc[t][1], acc[t][2], acc[t][3]);
    }
    __syncthreads();
    if (wh == 1) return;

    const float4* src4 = (const float4*)(xch + (wl * 32 + lane) * 16);
    unsigned mlo = 0u, mhi = 0u;
#pragma unroll
    for (int t = 0; t < 4; t++) {
        float4 pv = src4[t];
        int cb = t * 8 + 2 * q;
        float o0 = soff[cb], o1 = soff[cb + 1];
        mlo |= ((acc[t][0] + pv.x - o0) > 0.f ? 1u : 0u) << cb;
        mlo |= ((acc[t][1] + pv.y - o1) > 0.f ? 1u : 0u) << (cb + 1);
        mhi |= ((acc[t][2] + pv.z - o0) > 0.f ? 1u : 0u) << cb;
        mhi |= ((acc[t][3] + pv.w - o1) > 0.f ? 1u : 0u) << (cb + 1);
    }
    mlo |= __shfl_xor_sync(0xffffffffu, mlo, 1);
    mlo |= __shfl_xor_sync(0xffffffffu, mlo, 2);
    mhi |= __shfl_xor_sync(0xffffffffu, mhi, 1);
    mhi |= __shfl_xor_sync(0xffffffffu, mhi, 2);

    if (q == 0) {
        g_hash[rowA] = mlo;
        g_hash[rowB] = mhi;
        table_insert(rowA, mlo);
        table_insert(rowB, mhi);
    }
}

// ---------------------------------------------------------------------------
// Kernel 4: rewards. Unique keys -> 1.0; rare duplicates get exact rank.
// ---------------------------------------------------------------------------
__global__ void k_final(float* __restrict__ out) {
    int i = blockIdx.x * 256 + threadIdx.x;
    unsigned s = g_slot[i];
    float v = 1.0f;
    if (g_tcnt[s] != 1u) {
        unsigned long long my = ((unsigned long long)g_hash[i] << 6) | (unsigned long long)(i & 63);
        int c = 1;
        for (int j = 0; j < i; j++) {
            unsigned long long kj = ((unsigned long long)g_hash[j] << 6) | (unsigned long long)(j & 63);
            c += (kj == my) ? 1 : 0;
        }
        v = 1.0f / sqrtf((float)c);
    }
    out[i] = v;
}

// ---------------------------------------------------------------------------
// Launch (4 launches)
// ---------------------------------------------------------------------------
extern "C" void kernel_launch(void* const* d_in, const int* in_sizes, int n_in,
                              void* d_out, int out_size) {
    const float* x  = (const float*)d_in[0];
    const float* rp = (const float*)d_in[1];
    if (in_sizes[0] == N_FEAT * N_BINS) {   // defensive: swap if order differs
        const float* t = x; x = rp; rp = t;
    }
    float* out = (float*)d_out;

    cudaFuncSetAttribute(k_project, cudaFuncAttributeMaxDynamicSharedMemorySize, PROJ_SMEM);

    k_pre    <<<1280, 256>>>(x);
    k_scale  <<<64, 256>>>(rp);
    k_project<<<NTILE, 512, PROJ_SMEM>>>();
    k_final  <<<64, 256>>>(out);
}